// round 15
// baseline (speedup 1.0000x reference)
#include <cuda_runtime.h>
#include <cuda_fp16.h>
#include <math.h>
#include <stdint.h>

// ---------------------------------------------------------------------------
// Transformer block: x -> QKV -> attention -> +res -> LN1 -> FFN(gelu) -> +res -> LN2
// B=4 S=2048 H=1024 NH=16 HD=64 FF=4096.
// fp32 in/out; fp16 storage + fp16 mma.sync (fp32 accum); cp.async; ldmatrix;
// unnormalized exp2 softmax; l via ones-MMA; 2 CTAs/SM.
// R15: R13 config + attention 3-stage cp.async pipeline (64-row KV tiles).
// ---------------------------------------------------------------------------

#define Bc   4
#define Sc   2048
#define Hc   1024
#define NHc  16
#define HDc  64
#define FFc  4096
#define Nc   (Bc*Sc)   // 8192

#define QSCALE 0.1803368801111204f     // (1/sqrt(64)) * log2(e)
#define ONE_H2 0x3C003C00u

__device__ __align__(128) __half g_xh   [Nc*Hc];
__device__ __align__(128) __half g_qh   [Bc*NHc*Sc*HDc];
__device__ __align__(128) __half g_kh   [Bc*NHc*Sc*HDc];
__device__ __align__(128) __half g_vh   [Bc*NHc*Sc*HDc];
__device__ __align__(128) __half g_hh   [Nc*Hc];
__device__ __align__(128) __half g_ffnh [Nc*FFc];
__device__ __align__(128) __half g_atth [Nc*Hc];
__device__ __align__(128) __half g_wqkvt[3*Hc*Hc];
__device__ __align__(128) __half g_wit  [FFc*Hc];
__device__ __align__(128) __half g_wot  [Hc*FFc];

__device__ __forceinline__ uint32_t pack_h2(float x, float y) {
    __half2 h = __floats2half2_rn(x, y);
    return *(uint32_t*)&h;
}
__device__ __forceinline__ void mma_f16(float* d, const uint32_t* a, const uint32_t* b) {
    asm volatile(
        "mma.sync.aligned.m16n8k16.row.col.f32.f16.f16.f32 "
        "{%0,%1,%2,%3}, {%4,%5,%6,%7}, {%8,%9}, {%0,%1,%2,%3};"
        : "+f"(d[0]), "+f"(d[1]), "+f"(d[2]), "+f"(d[3])
        : "r"(a[0]), "r"(a[1]), "r"(a[2]), "r"(a[3]), "r"(b[0]), "r"(b[1]));
}
__device__ __forceinline__ void ldm_x4(uint32_t* r, const __half* p) {
    uint32_t a = (uint32_t)__cvta_generic_to_shared(p);
    asm volatile("ldmatrix.sync.aligned.m8n8.x4.shared.b16 {%0,%1,%2,%3}, [%4];"
        : "=r"(r[0]), "=r"(r[1]), "=r"(r[2]), "=r"(r[3]) : "r"(a));
}
__device__ __forceinline__ void ldm_x4_trans(uint32_t* r, const __half* p) {
    uint32_t a = (uint32_t)__cvta_generic_to_shared(p);
    asm volatile("ldmatrix.sync.aligned.m8n8.x4.trans.shared.b16 {%0,%1,%2,%3}, [%4];"
        : "=r"(r[0]), "=r"(r[1]), "=r"(r[2]), "=r"(r[3]) : "r"(a));
}
__device__ __forceinline__ uint32_t ex2_h2(uint32_t in) {
    uint32_t o; asm("ex2.approx.f16x2 %0, %1;" : "=r"(o) : "r"(in)); return o;
}

#define CP16(dst_u32, src) \
    asm volatile("cp.async.cg.shared.global [%0], [%1], 16;" :: "r"(dst_u32), "l"(src))
#define CP_COMMIT() asm volatile("cp.async.commit_group;" ::: "memory")
#define CP_WAIT0()  asm volatile("cp.async.wait_group 0;" ::: "memory")
#define CP_WAIT1()  asm volatile("cp.async.wait_group 1;" ::: "memory")

__device__ __forceinline__ float gelu_exact(float x) {
    return 0.5f * x * (1.0f + erff(x * 0.70710678118654752f));
}

// ===========================================================================
// fp16 GEMM (R13): Block 128x128x64, 256 thr, warp tile 64x32, 3-stage,
// 2 CTAs/SM. One sync + one wait per 64-wide K-tile.
// ===========================================================================
#define GT_BM 128
#define GT_BN 128
#define GT_BK 64
#define GT_PAD 72
#define GT_SA (GT_BM*GT_PAD)
#define GT_STG (2*GT_SA)
#define GT_SMEM (3*GT_STG*2)               // 110592 B

template<int MODE>
__global__ __launch_bounds__(256, 2)
void mgemm(const __half* __restrict__ A, const __half* __restrict__ Bw,
           const float* __restrict__ bias0, const float* __restrict__ bias1,
           const float* __restrict__ bias2,
           __half* __restrict__ o0, __half* __restrict__ o1, __half* __restrict__ o2,
           int K, int Mout)
{
    extern __shared__ __half smh[];
    const uint32_t sm_u = (uint32_t)__cvta_generic_to_shared(smh);

    const int tid  = threadIdx.x;
    const int wid  = tid >> 5;
    const int lane = tid & 31;
    const int g    = lane >> 2;
    const int tig  = lane & 3;
    const int wm   = wid & 1;
    const int wn   = wid >> 1;
    const int l15  = lane & 15;
    const int lhi  = (lane >> 4) << 3;

    const int row0 = blockIdx.y * GT_BM;
    const int col0 = blockIdx.x * GT_BN;

    const __half* Ab = A  + (size_t)row0 * K;
    const __half* Bb = Bw + (size_t)col0 * K;

    float acc[4][4][4];
#pragma unroll
    for (int mt = 0; mt < 4; mt++)
#pragma unroll
        for (int nt = 0; nt < 4; nt++)
#pragma unroll
            for (int e = 0; e < 4; e++) acc[mt][nt][e] = 0.f;

    const int KT = K / GT_BK;

    auto issue = [&](int kt, int s) {
        const __half* ap = Ab + kt * GT_BK;
        const __half* bp = Bb + kt * GT_BK;
        const uint32_t abase = sm_u + (uint32_t)(s * GT_STG) * 2;
        const uint32_t bbase = abase + GT_SA * 2;
#pragma unroll
        for (int i = 0; i < 4; i++) {
            const int idx = tid + (i << 8);
            const int r = idx >> 3, c = (idx & 7) << 3;
            const uint32_t off = (uint32_t)(r * GT_PAD + c) * 2;
            CP16(abase + off, ap + (size_t)r * K + c);
            CP16(bbase + off, bp + (size_t)r * K + c);
        }
    };

    issue(0, 0); CP_COMMIT();
    issue(1, 1); CP_COMMIT();

    for (int kt = 0; kt < KT; kt++) {
        const int cur = kt % 3;
        if (kt + 1 < KT) CP_WAIT1(); else CP_WAIT0();
        __syncthreads();
        if (kt + 2 < KT) { issue(kt + 2, (kt + 2) % 3); CP_COMMIT(); }

        const __half* As = smh + cur * GT_STG;
        const __half* Bs = As + GT_SA;
#pragma unroll
        for (int ks = 0; ks < 4; ks++) {
            const int kb = ks * 16;
            uint32_t af[4][4], bq[2][4];
#pragma unroll
            for (int mt = 0; mt < 4; mt++)
                ldm_x4(af[mt], &As[(wm * 64 + mt * 16 + l15) * GT_PAD + kb + lhi]);
#pragma unroll
            for (int np = 0; np < 2; np++)
                ldm_x4(bq[np], &Bs[(wn * 32 + np * 16 + l15) * GT_PAD + kb + lhi]);
#pragma unroll
            for (int mt = 0; mt < 4; mt++)
#pragma unroll
                for (int nt = 0; nt < 4; nt++) {
                    uint32_t bb[2] = { bq[nt >> 1][nt & 1], bq[nt >> 1][(nt & 1) + 2] };
                    mma_f16(acc[mt][nt], af[mt], bb);
                }
        }
    }

    const int trow = row0 + wm * 64 + g;
    const int tcol = col0 + wn * 32 + 2 * tig;

#pragma unroll
    for (int mt = 0; mt < 4; mt++) {
#pragma unroll
        for (int half_ = 0; half_ < 2; half_++) {
            const int row = trow + mt * 16 + half_ * 8;
            const int bb_ = row >> 11, ss_ = row & 2047;
#pragma unroll
            for (int nt = 0; nt < 4; nt++) {
                const int gc = tcol + nt * 8;
                float v0 = acc[mt][nt][half_ * 2 + 0];
                float v1 = acc[mt][nt][half_ * 2 + 1];
                if (MODE == 1) {
                    const int t  = col0 >> 10;
                    const int ct = gc & 1023;
                    const float* bp = (t == 0) ? bias0 : (t == 1 ? bias1 : bias2);
                    __half* ob = (t == 0) ? o0 : (t == 1 ? o1 : o2);
                    v0 += bp[ct]; v1 += bp[ct + 1];
                    if (t == 0) { v0 *= QSCALE; v1 *= QSCALE; }
                    const int hh = ct >> 6, d0 = ct & 63;
                    __half* p = ob + (((size_t)(bb_ * NHc + hh) * Sc + ss_) << 6) + d0;
                    *(uint32_t*)p = pack_h2(v0, v1);
                } else {
                    v0 += bias0[gc]; v1 += bias0[gc + 1];
                    if (MODE == 2) { v0 = gelu_exact(v0); v1 = gelu_exact(v1); }
                    *(uint32_t*)(o0 + (size_t)row * Mout + gc) = pack_h2(v0, v1);
                }
            }
        }
    }
}

// ===========================================================================
// x fp32 -> fp16
// ===========================================================================
__global__ void cvt_h(const float* __restrict__ src, __half* __restrict__ dst)
{
    const int i = blockIdx.x * blockDim.x + threadIdx.x;
    float4 a = ((const float4*)src)[2*i];
    float4 b = ((const float4*)src)[2*i + 1];
    uint4 u = { pack_h2(a.x, a.y), pack_h2(a.z, a.w),
                pack_h2(b.x, b.y), pack_h2(b.z, b.w) };
    ((uint4*)dst)[i] = u;
}

// ===========================================================================
// Transpose + fp16
// ===========================================================================
__global__ void transp_h(const float* __restrict__ W, __half* __restrict__ Wt, int K, int M)
{
    __shared__ float t[32][33];
    const int bx = blockIdx.x << 5, by = blockIdx.y << 5;
    const int x = threadIdx.x, y = threadIdx.y;
#pragma unroll
    for (int j = 0; j < 32; j += 8)
        t[y + j][x] = W[(size_t)(by + y + j) * M + bx + x];
    __syncthreads();
#pragma unroll
    for (int j = 0; j < 32; j += 8)
        Wt[(size_t)(bx + y + j) * K + by + x] = __float2half_rn(t[x][y + j]);
}

__global__ void transp3_h(const float* __restrict__ W0, const float* __restrict__ W1,
                          const float* __restrict__ W2, __half* __restrict__ Wt)
{
    __shared__ float t[32][33];
    const float* W = (blockIdx.z == 0) ? W0 : (blockIdx.z == 1 ? W1 : W2);
    __half* D = Wt + (size_t)blockIdx.z * Hc * Hc;
    const int bx = blockIdx.x << 5, by = blockIdx.y << 5;
    const int x = threadIdx.x, y = threadIdx.y;
#pragma unroll
    for (int j = 0; j < 32; j += 8)
        t[y + j][x] = W[(size_t)(by + y + j) * Hc + bx + x];
    __syncthreads();
#pragma unroll
    for (int j = 0; j < 32; j += 8)
        D[(size_t)(bx + y + j) * Hc + by + x] = __float2half_rn(t[x][y + j]);
}

// ===========================================================================
// Flash attention: 256 thr, 8 warps x 16 queries, 64-row KV tiles,
// 3-stage cp.async pipeline, ldmatrix, unnormalized P = 2^s, l via ones-MMA,
// 2 CTAs/SM (54KB smem).
// ===========================================================================
#define AT_PAD 72
#define AT_TS  (64*AT_PAD)                  // halves per K or V tile
#define AT_STG (2*AT_TS)                    // halves per stage (K+V)
#define AT_SMEM (3*AT_STG*2)                // 55296 B

__global__ __launch_bounds__(256, 2)
void attn_k()
{
    extern __shared__ __half smh[];
    const uint32_t sm_u = (uint32_t)__cvta_generic_to_shared(smh);

    const int bh = blockIdx.y;
    const __half* Qg = g_qh + (size_t)bh * Sc * HDc;
    const __half* Kg = g_kh + (size_t)bh * Sc * HDc;
    const __half* Vg = g_vh + (size_t)bh * Sc * HDc;
    const int q0 = blockIdx.x * 128;

    const int tid  = threadIdx.x;
    const int w    = tid >> 5;
    const int lane = tid & 31;
    const int g    = lane >> 2;
    const int tig  = lane & 3;
    const int rw   = w * 16;
    const int l15  = lane & 15;
    const int lhi  = (lane >> 4) << 3;

    uint32_t qf[4][4];
    {
        const __half* Qr = Qg + (size_t)(q0 + rw) * HDc;
#pragma unroll
        for (int kg = 0; kg < 4; kg++) {
            const int c = kg * 16 + 2 * tig;
            qf[kg][0] = *(const uint32_t*)&Qr[(size_t)(g    ) * HDc + c    ];
            qf[kg][1] = *(const uint32_t*)&Qr[(size_t)(g + 8) * HDc + c    ];
            qf[kg][2] = *(const uint32_t*)&Qr[(size_t)(g    ) * HDc + c + 8];
            qf[kg][3] = *(const uint32_t*)&Qr[(size_t)(g + 8) * HDc + c + 8];
        }
    }

    float oacc[8][4];
#pragma unroll
    for (int nt = 0; nt < 8; nt++)
#pragma unroll
        for (int e = 0; e < 4; e++) oacc[nt][e] = 0.f;
    float lacc[4] = {0.f, 0.f, 0.f, 0.f};
    const uint32_t ones[2] = { ONE_H2, ONE_H2 };

    // load one 64-row KV tile into stage s
    auto issue_kv = [&](int kt, int s) {
        const uint32_t kbase = sm_u + (uint32_t)(s * AT_STG) * 2;
        const uint32_t vbase = kbase + AT_TS * 2;
#pragma unroll
        for (int i = 0; i < 2; i++) {
            const int idx = tid + (i << 8);
            const int r = idx >> 3, c = (idx & 7) << 3;
            const uint32_t off = (uint32_t)(r * AT_PAD + c) * 2;
            const size_t gsrc = (size_t)(kt * 64 + r) * HDc + c;
            CP16(kbase + off, Kg + gsrc);
            CP16(vbase + off, Vg + gsrc);
        }
    };

    const int KT = Sc / 64;
    issue_kv(0, 0); CP_COMMIT();
    issue_kv(1, 1); CP_COMMIT();

    for (int kt = 0; kt < KT; kt++) {
        const int cur = kt % 3;
        if (kt + 1 < KT) CP_WAIT1(); else CP_WAIT0();
        __syncthreads();
        if (kt + 2 < KT) { issue_kv(kt + 2, (kt + 2) % 3); CP_COMMIT(); }

        const __half* Ks = smh + cur * AT_STG;
        const __half* Vs = Ks + AT_TS;

        // ---- S' = (log2e/8) Q K^T ----
        float sacc[8][4];
#pragma unroll
        for (int nt = 0; nt < 8; nt++)
#pragma unroll
            for (int e = 0; e < 4; e++) sacc[nt][e] = 0.f;

#pragma unroll
        for (int kg = 0; kg < 4; kg++) {
            const int kb = kg * 16;
#pragma unroll
            for (int ntp = 0; ntp < 4; ntp++) {
                uint32_t kr[4];
                ldm_x4(kr, &Ks[(ntp * 16 + l15) * AT_PAD + kb + lhi]);
                uint32_t b0[2] = { kr[0], kr[2] };
                uint32_t b1[2] = { kr[1], kr[3] };
                mma_f16(sacc[2*ntp    ], qf[kg], b0);
                mma_f16(sacc[2*ntp + 1], qf[kg], b1);
            }
        }

        // ---- P = 2^s ----
        uint32_t ph[8][2];
#pragma unroll
        for (int nt = 0; nt < 8; nt++) {
            ph[nt][0] = ex2_h2(pack_h2(sacc[nt][0], sacc[nt][1]));
            ph[nt][1] = ex2_h2(pack_h2(sacc[nt][2], sacc[nt][3]));
        }

        // ---- O += P V ; l += P @ ones ----
#pragma unroll
        for (int kg = 0; kg < 4; kg++) {
            const int kb = kg * 16;
            uint32_t pf[4] = { ph[2*kg][0], ph[2*kg][1], ph[2*kg+1][0], ph[2*kg+1][1] };
            mma_f16(lacc, pf, ones);
#pragma unroll
            for (int ntp = 0; ntp < 4; ntp++) {
                uint32_t vr[4];
                ldm_x4_trans(vr, &Vs[(kb + l15) * AT_PAD + ntp * 16 + lhi]);
                mma_f16(oacc[2*ntp    ], pf, vr    );
                mma_f16(oacc[2*ntp + 1], pf, vr + 2);
            }
        }
    }

    // ---- epilogue ----
    const float inv0 = 1.0f / lacc[0];
    const float inv1 = 1.0f / lacc[2];
    const int b = bh >> 4, h = bh & 15;
    const int s0 = q0 + rw + g;
    const int s1 = s0 + 8;
#pragma unroll
    for (int nt = 0; nt < 8; nt++) {
        const int col = h * 64 + nt * 8 + 2 * tig;
        *(uint32_t*)&g_atth[(size_t)(b * Sc + s0) * Hc + col] =
            pack_h2(oacc[nt][0] * inv0, oacc[nt][1] * inv0);
        *(uint32_t*)&g_atth[(size_t)(b * Sc + s1) * Hc + col] =
            pack_h2(oacc[nt][2] * inv1, oacc[nt][3] * inv1);
    }
}

// ===========================================================================
// LN kernels.
// ===========================================================================
__global__ void ln_fh(const float* __restrict__ X, const __half* __restrict__ Y,
                      const float* __restrict__ g, const float* __restrict__ bta,
                      __half* __restrict__ out16)
{
    const int row = blockIdx.x;
    const int tid = threadIdx.x;

    float4 a = ((const float4*)(X + (size_t)row * Hc))[tid];
    uint2 yu = *(const uint2*)&Y[(size_t)row * Hc + tid * 4];
    float2 y0 = __half22float2(*(__half2*)&yu.x);
    float2 y1 = __half22float2(*(__half2*)&yu.y);
    float4 s = make_float4(a.x + y0.x, a.y + y0.y, a.z + y1.x, a.w + y1.y);

    float sum = s.x + s.y + s.z + s.w;
    float sq  = s.x*s.x + s.y*s.y + s.z*s.z + s.w*s.w;
#pragma unroll
    for (int off = 1; off < 32; off <<= 1) {
        sum += __shfl_xor_sync(0xffffffffu, sum, off);
        sq  += __shfl_xor_sync(0xffffffffu, sq,  off);
    }
    __shared__ float ssum[8], ssq[8];
    if ((tid & 31) == 0) { ssum[tid >> 5] = sum; ssq[tid >> 5] = sq; }
    __syncthreads();
    float fs = 0.f, fq = 0.f;
#pragma unroll
    for (int w = 0; w < 8; w++) { fs += ssum[w]; fq += ssq[w]; }

    const float mean = fs * (1.0f / Hc);
    const float var  = fq * (1.0f / Hc) - mean * mean;
    const float rstd = rsqrtf(var + 1e-5f);

    float4 gg = ((const float4*)g)[tid];
    float4 bb = ((const float4*)bta)[tid];
    float4 o = make_float4((s.x - mean) * rstd * gg.x + bb.x,
                           (s.y - mean) * rstd * gg.y + bb.y,
                           (s.z - mean) * rstd * gg.z + bb.z,
                           (s.w - mean) * rstd * gg.w + bb.w);
    uint2 u = { pack_h2(o.x, o.y), pack_h2(o.z, o.w) };
    *(uint2*)&out16[(size_t)row * Hc + tid * 4] = u;
}

__global__ void ln_hh(const __half* __restrict__ X, const __half* __restrict__ Y,
                      const float* __restrict__ g, const float* __restrict__ bta,
                      float* __restrict__ out)
{
    const int row = blockIdx.x;
    const int tid = threadIdx.x;

    uint2 xu = *(const uint2*)&X[(size_t)row * Hc + tid * 4];
    uint2 yu = *(const uint2*)&Y[(size_t)row * Hc + tid * 4];
    float2 x0 = __half22float2(*(__half2*)&xu.x);
    float2 x1 = __half22float2(*(__half2*)&xu.y);
    float2 y0 = __half22float2(*(__half2*)&yu.x);
    float2 y1 = __half22float2(*(__half2*)&yu.y);
    float4 s = make_float4(x0.x + y0.x, x0.y + y0.y, x1.x + y1.x, x1.y + y1.y);

    float sum = s.x + s.y + s.z + s.w;
    float sq  = s.x*s.x + s.y*s.y + s.z*s.z + s.w*s.w;
#pragma unroll
    for (int off = 1; off < 32; off <<= 1) {
        sum += __shfl_xor_sync(0xffffffffu, sum, off);
        sq  += __shfl_xor_sync(0xffffffffu, sq,  off);
    }
    __shared__ float ssum[8], ssq[8];
    if ((tid & 31) == 0) { ssum[tid >> 5] = sum; ssq[tid >> 5] = sq; }
    __syncthreads();
    float fs = 0.f, fq = 0.f;
#pragma unroll
    for (int w = 0; w < 8; w++) { fs += ssum[w]; fq += ssq[w]; }

    const float mean = fs * (1.0f / Hc);
    const float var  = fq * (1.0f / Hc) - mean * mean;
    const float rstd = rsqrtf(var + 1e-5f);

    float4 gg = ((const float4*)g)[tid];
    float4 bb = ((const float4*)bta)[tid];
    float4 o = make_float4((s.x - mean) * rstd * gg.x + bb.x,
                           (s.y - mean) * rstd * gg.y + bb.y,
                           (s.z - mean) * rstd * gg.z + bb.z,
                           (s.w - mean) * rstd * gg.w + bb.w);
    ((float4*)(out + (size_t)row * Hc))[tid] = o;
}

// ===========================================================================
extern "C" void kernel_launch(void* const* d_in, const int* in_sizes, int n_in,
                              void* d_out, int out_size)
{
    const float* x  = (const float*)d_in[0];
    const float* Wq = (const float*)d_in[1];
    const float* bq = (const float*)d_in[2];
    const float* Wk = (const float*)d_in[3];
    const float* bk = (const float*)d_in[4];
    const float* Wv = (const float*)d_in[5];
    const float* bv = (const float*)d_in[6];
    const float* Wi = (const float*)d_in[7];
    const float* bi = (const float*)d_in[8];
    const float* Wo = (const float*)d_in[9];
    const float* bo = (const float*)d_in[10];
    const float* g1 = (const float*)d_in[11];
    const float* b1 = (const float*)d_in[12];
    const float* g2 = (const float*)d_in[13];
    const float* b2 = (const float*)d_in[14];
    float* out = (float*)d_out;

    __half *xh, *qh, *kh, *vh, *hh, *ffnh, *atth, *wqkvt, *wit, *wot;
    cudaGetSymbolAddress((void**)&xh,    g_xh);
    cudaGetSymbolAddress((void**)&qh,    g_qh);
    cudaGetSymbolAddress((void**)&kh,    g_kh);
    cudaGetSymbolAddress((void**)&vh,    g_vh);
    cudaGetSymbolAddress((void**)&hh,    g_hh);
    cudaGetSymbolAddress((void**)&ffnh,  g_ffnh);
    cudaGetSymbolAddress((void**)&atth,  g_atth);
    cudaGetSymbolAddress((void**)&wqkvt, g_wqkvt);
    cudaGetSymbolAddress((void**)&wit,   g_wit);
    cudaGetSymbolAddress((void**)&wot,   g_wot);

    cudaFuncSetAttribute(attn_k,   cudaFuncAttributeMaxDynamicSharedMemorySize, AT_SMEM);
    cudaFuncSetAttribute(mgemm<0>, cudaFuncAttributeMaxDynamicSharedMemorySize, GT_SMEM);
    cudaFuncSetAttribute(mgemm<1>, cudaFuncAttributeMaxDynamicSharedMemorySize, GT_SMEM);
    cudaFuncSetAttribute(mgemm<2>, cudaFuncAttributeMaxDynamicSharedMemorySize, GT_SMEM);

    // x -> fp16
    cvt_h<<<Nc*Hc/(256*8), 256>>>(x, xh);

    // weight transposes (fp32 W[K,M] -> fp16 Wt[M,K])
    dim3 tb(32, 8);
    transp3_h<<<dim3(Hc/32, Hc/32, 3), tb>>>(Wq, Wk, Wv, wqkvt);
    transp_h<<<dim3(FFc/32, Hc/32),  tb>>>(Wi, wit, Hc,  FFc);
    transp_h<<<dim3(Hc/32,  FFc/32), tb>>>(Wo, wot, FFc, Hc);

    // fused QKV projection -> fp16 q(prescaled)/k/v scatter [b,h,s,d]
    mgemm<1><<<dim3(3*Hc/GT_BN, Nc/GT_BM), 256, GT_SMEM>>>(
        xh, wqkvt, bq, bk, bv, qh, kh, vh, Hc, 3*Hc);

    // attention -> fp16 atth
    attn_k<<<dim3(Sc / 128, Bc * NHc), 256, AT_SMEM>>>();

    // residual + LN1 -> fp16 hh
    ln_fh<<<Nc, 256>>>(x, atth, g1, b1, hh);

    // FFN (fp16 throughout)
    mgemm<2><<<dim3(FFc/GT_BN, Nc/GT_BM), 256, GT_SMEM>>>(
        hh, wit, bi, bi, bi, ffnh, ffnh, ffnh, Hc, FFc);
    mgemm<0><<<dim3(Hc/GT_BN, Nc/GT_BM), 256, GT_SMEM>>>(
        ffnh, wot, bo, bo, bo, atth, atth, atth, FFc, Hc);

    // residual + LN2 -> final fp32 out
    ln_hh<<<Nc, 256>>>(hh, atth, g2, b2, out);
}

// round 16
// speedup vs baseline: 1.1158x; 1.1158x over previous
#include <cuda_runtime.h>
#include <cuda_fp16.h>
#include <math.h>
#include <stdint.h>

// ---------------------------------------------------------------------------
// Transformer block: x -> QKV -> attention -> +res -> LN1 -> FFN(gelu) -> +res -> LN2
// B=4 S=2048 H=1024 NH=16 HD=64 FF=4096.
// fp32 in/out; fp16 storage + fp16 mma.sync (fp32 accum); cp.async; ldmatrix;
// unnormalized exp2 softmax; l via ones-MMA; 2 CTAs/SM.
// R16: weights kept in native [K,M] fp16 (no transpose); GEMM B-fragments via
// ldmatrix.trans (same pattern as attention PV). Attention = R13 (2-stage).
// ---------------------------------------------------------------------------

#define Bc   4
#define Sc   2048
#define Hc   1024
#define NHc  16
#define HDc  64
#define FFc  4096
#define Nc   (Bc*Sc)   // 8192

#define QSCALE 0.1803368801111204f     // (1/sqrt(64)) * log2(e)
#define ONE_H2 0x3C003C00u

__device__ __align__(128) __half g_xh   [Nc*Hc];
__device__ __align__(128) __half g_qh   [Bc*NHc*Sc*HDc];
__device__ __align__(128) __half g_kh   [Bc*NHc*Sc*HDc];
__device__ __align__(128) __half g_vh   [Bc*NHc*Sc*HDc];
__device__ __align__(128) __half g_hh   [Nc*Hc];
__device__ __align__(128) __half g_ffnh [Nc*FFc];
__device__ __align__(128) __half g_atth [Nc*Hc];
__device__ __align__(128) __half g_wqkv [Hc*3*Hc];     // [1024][3072] fp16, native K-major
__device__ __align__(128) __half g_wi   [Hc*FFc];      // [1024][4096]
__device__ __align__(128) __half g_wo   [FFc*Hc];      // [4096][1024]

__device__ __forceinline__ uint32_t pack_h2(float x, float y) {
    __half2 h = __floats2half2_rn(x, y);
    return *(uint32_t*)&h;
}
__device__ __forceinline__ void mma_f16(float* d, const uint32_t* a, const uint32_t* b) {
    asm volatile(
        "mma.sync.aligned.m16n8k16.row.col.f32.f16.f16.f32 "
        "{%0,%1,%2,%3}, {%4,%5,%6,%7}, {%8,%9}, {%0,%1,%2,%3};"
        : "+f"(d[0]), "+f"(d[1]), "+f"(d[2]), "+f"(d[3])
        : "r"(a[0]), "r"(a[1]), "r"(a[2]), "r"(a[3]), "r"(b[0]), "r"(b[1]));
}
__device__ __forceinline__ void ldm_x4(uint32_t* r, const __half* p) {
    uint32_t a = (uint32_t)__cvta_generic_to_shared(p);
    asm volatile("ldmatrix.sync.aligned.m8n8.x4.shared.b16 {%0,%1,%2,%3}, [%4];"
        : "=r"(r[0]), "=r"(r[1]), "=r"(r[2]), "=r"(r[3]) : "r"(a));
}
__device__ __forceinline__ void ldm_x4_trans(uint32_t* r, const __half* p) {
    uint32_t a = (uint32_t)__cvta_generic_to_shared(p);
    asm volatile("ldmatrix.sync.aligned.m8n8.x4.trans.shared.b16 {%0,%1,%2,%3}, [%4];"
        : "=r"(r[0]), "=r"(r[1]), "=r"(r[2]), "=r"(r[3]) : "r"(a));
}
__device__ __forceinline__ uint32_t ex2_h2(uint32_t in) {
    uint32_t o; asm("ex2.approx.f16x2 %0, %1;" : "=r"(o) : "r"(in)); return o;
}

#define CP16(dst_u32, src) \
    asm volatile("cp.async.cg.shared.global [%0], [%1], 16;" :: "r"(dst_u32), "l"(src))
#define CP_COMMIT() asm volatile("cp.async.commit_group;" ::: "memory")
#define CP_WAIT0()  asm volatile("cp.async.wait_group 0;" ::: "memory")
#define CP_WAIT1()  asm volatile("cp.async.wait_group 1;" ::: "memory")

__device__ __forceinline__ float gelu_exact(float x) {
    return 0.5f * x * (1.0f + erff(x * 0.70710678118654752f));
}

// ===========================================================================
// fp16 GEMM: out = A[N,K] @ W[K,M] + bias.  W native K-major fp16.
// Block 128x128x64, 256 thr (8 warps 2x4), warp tile 64x32, 3-stage cp.async,
// 2 CTAs/SM. A frags via ldmatrix; B frags via ldmatrix.trans from [k][m] tile.
// MODE 0: plain fp16 out; MODE 1: qkv scatter (q pre-scaled); MODE 2: gelu.
// Mout = W row stride (M) for all modes.
// ===========================================================================
#define GT_BM 128
#define GT_BN 128
#define GT_BK 64
#define GT_APAD 72                          // A row stride (halves)
#define GT_BPAD 136                         // B row stride (halves)
#define GT_SA (GT_BM*GT_APAD)               // 9216 halves
#define GT_SB (GT_BK*GT_BPAD)               // 8704 halves
#define GT_STG (GT_SA+GT_SB)                // 17920 halves / stage
#define GT_SMEM (3*GT_STG*2)                // 107520 B

template<int MODE>
__global__ __launch_bounds__(256, 2)
void mgemm(const __half* __restrict__ A, const __half* __restrict__ Bw,
           const float* __restrict__ bias0, const float* __restrict__ bias1,
           const float* __restrict__ bias2,
           __half* __restrict__ o0, __half* __restrict__ o1, __half* __restrict__ o2,
           int K, int Mout)
{
    extern __shared__ __half smh[];
    const uint32_t sm_u = (uint32_t)__cvta_generic_to_shared(smh);

    const int tid  = threadIdx.x;
    const int wid  = tid >> 5;
    const int lane = tid & 31;
    const int g    = lane >> 2;
    const int tig  = lane & 3;
    const int wm   = wid & 1;
    const int wn   = wid >> 1;
    const int l15  = lane & 15;
    const int lhi  = (lane >> 4) << 3;

    const int row0 = blockIdx.y * GT_BM;
    const int col0 = blockIdx.x * GT_BN;

    const __half* Ab = A  + (size_t)row0 * K;
    const __half* Bb = Bw + col0;

    float acc[4][4][4];
#pragma unroll
    for (int mt = 0; mt < 4; mt++)
#pragma unroll
        for (int nt = 0; nt < 4; nt++)
#pragma unroll
            for (int e = 0; e < 4; e++) acc[mt][nt][e] = 0.f;

    const int KT = K / GT_BK;

    auto issue = [&](int kt, int s) {
        const __half* ap = Ab + kt * GT_BK;
        const __half* bp = Bb + (size_t)(kt * GT_BK) * Mout;
        const uint32_t abase = sm_u + (uint32_t)(s * GT_STG) * 2;
        const uint32_t bbase = abase + GT_SA * 2;
#pragma unroll
        for (int i = 0; i < 4; i++) {
            const int idx = tid + (i << 8);
            {   // A: 128 rows x 64 halves
                const int r = idx >> 3, c = (idx & 7) << 3;
                CP16(abase + (uint32_t)(r * GT_APAD + c) * 2, ap + (size_t)r * K + c);
            }
            {   // B: 64 rows x 128 halves
                const int r = idx >> 4, c = (idx & 15) << 3;
                CP16(bbase + (uint32_t)(r * GT_BPAD + c) * 2, bp + (size_t)r * Mout + c);
            }
        }
    };

    issue(0, 0); CP_COMMIT();
    issue(1, 1); CP_COMMIT();

    for (int kt = 0; kt < KT; kt++) {
        const int cur = kt % 3;
        if (kt + 1 < KT) CP_WAIT1(); else CP_WAIT0();
        __syncthreads();
        if (kt + 2 < KT) { issue(kt + 2, (kt + 2) % 3); CP_COMMIT(); }

        const __half* As = smh + cur * GT_STG;
        const __half* Bs = As + GT_SA;
#pragma unroll
        for (int ks = 0; ks < 4; ks++) {
            const int kb = ks * 16;
            uint32_t af[4][4], bq[2][4];
#pragma unroll
            for (int mt = 0; mt < 4; mt++)
                ldm_x4(af[mt], &As[(wm * 64 + mt * 16 + l15) * GT_APAD + kb + lhi]);
#pragma unroll
            for (int np = 0; np < 2; np++)
                ldm_x4_trans(bq[np], &Bs[(kb + l15) * GT_BPAD + wn * 32 + np * 16 + lhi]);
#pragma unroll
            for (int mt = 0; mt < 4; mt++)
#pragma unroll
                for (int nt = 0; nt < 4; nt++) {
                    uint32_t bb[2] = { bq[nt >> 1][(nt & 1) * 2], bq[nt >> 1][(nt & 1) * 2 + 1] };
                    mma_f16(acc[mt][nt], af[mt], bb);
                }
        }
    }

    const int trow = row0 + wm * 64 + g;
    const int tcol = col0 + wn * 32 + 2 * tig;

#pragma unroll
    for (int mt = 0; mt < 4; mt++) {
#pragma unroll
        for (int half_ = 0; half_ < 2; half_++) {
            const int row = trow + mt * 16 + half_ * 8;
            const int bb_ = row >> 11, ss_ = row & 2047;
#pragma unroll
            for (int nt = 0; nt < 4; nt++) {
                const int gc = tcol + nt * 8;
                float v0 = acc[mt][nt][half_ * 2 + 0];
                float v1 = acc[mt][nt][half_ * 2 + 1];
                if (MODE == 1) {
                    const int t  = gc >> 10;
                    const int ct = gc & 1023;
                    const float* bp = (t == 0) ? bias0 : (t == 1 ? bias1 : bias2);
                    __half* ob = (t == 0) ? o0 : (t == 1 ? o1 : o2);
                    v0 += bp[ct]; v1 += bp[ct + 1];
                    if (t == 0) { v0 *= QSCALE; v1 *= QSCALE; }
                    const int hh = ct >> 6, d0 = ct & 63;
                    __half* p = ob + (((size_t)(bb_ * NHc + hh) * Sc + ss_) << 6) + d0;
                    *(uint32_t*)p = pack_h2(v0, v1);
                } else {
                    v0 += bias0[gc]; v1 += bias0[gc + 1];
                    if (MODE == 2) { v0 = gelu_exact(v0); v1 = gelu_exact(v1); }
                    *(uint32_t*)(o0 + (size_t)row * Mout + gc) = pack_h2(v0, v1);
                }
            }
        }
    }
}

// ===========================================================================
// Streaming fp32 -> fp16 (8 elements/thread)
// ===========================================================================
__global__ void cvt_h(const float* __restrict__ src, __half* __restrict__ dst)
{
    const int i = blockIdx.x * blockDim.x + threadIdx.x;
    float4 a = ((const float4*)src)[2*i];
    float4 b = ((const float4*)src)[2*i + 1];
    uint4 u = { pack_h2(a.x, a.y), pack_h2(a.z, a.w),
                pack_h2(b.x, b.y), pack_h2(b.z, b.w) };
    ((uint4*)dst)[i] = u;
}

// Interleave Wq|Wk|Wv [1024][1024] fp32 -> dst [1024][3072] fp16
__global__ void cvt_w3(const float* __restrict__ W0, const float* __restrict__ W1,
                       const float* __restrict__ W2, __half* __restrict__ dst)
{
    const float* W = (blockIdx.z == 0) ? W0 : (blockIdx.z == 1 ? W1 : W2);
    const int i = blockIdx.x * blockDim.x + threadIdx.x;   // 8 elems each
    const int e = i * 8;
    const int k = e >> 10, m = e & 1023;
    float4 a = *(const float4*)(W + e);
    float4 b = *(const float4*)(W + e + 4);
    uint4 u = { pack_h2(a.x, a.y), pack_h2(a.z, a.w),
                pack_h2(b.x, b.y), pack_h2(b.z, b.w) };
    *(uint4*)&dst[(size_t)k * 3072 + blockIdx.z * 1024 + m] = u;
}

// ===========================================================================
// Flash attention (R13): 256 thr, 8 warps x 16 queries, 64-row KV tiles,
// cp.async dbl-buf, ldmatrix, unnormalized P = 2^s, l via ones-MMA, 2 CTAs/SM.
// ===========================================================================
#define AT_PAD 72
#define AT_TS  (64*AT_PAD)
#define AT_SMEM (4*AT_TS*2)     // 36864 B

__global__ __launch_bounds__(256, 2)
void attn_k()
{
    extern __shared__ __half smh[];
    __half* KS[2] = { smh,            smh + 2*AT_TS };
    __half* VS[2] = { smh + AT_TS,    smh + 3*AT_TS };
    uint32_t ks_u[2], vs_u[2];
    ks_u[0] = (uint32_t)__cvta_generic_to_shared(KS[0]);
    ks_u[1] = (uint32_t)__cvta_generic_to_shared(KS[1]);
    vs_u[0] = (uint32_t)__cvta_generic_to_shared(VS[0]);
    vs_u[1] = (uint32_t)__cvta_generic_to_shared(VS[1]);

    const int bh = blockIdx.y;
    const __half* Qg = g_qh + (size_t)bh * Sc * HDc;
    const __half* Kg = g_kh + (size_t)bh * Sc * HDc;
    const __half* Vg = g_vh + (size_t)bh * Sc * HDc;
    const int q0 = blockIdx.x * 128;

    const int tid  = threadIdx.x;
    const int w    = tid >> 5;
    const int lane = tid & 31;
    const int g    = lane >> 2;
    const int tig  = lane & 3;
    const int rw   = w * 16;
    const int l15  = lane & 15;
    const int lhi  = (lane >> 4) << 3;

    uint32_t qf[4][4];
    {
        const __half* Qr = Qg + (size_t)(q0 + rw) * HDc;
#pragma unroll
        for (int kg = 0; kg < 4; kg++) {
            const int c = kg * 16 + 2 * tig;
            qf[kg][0] = *(const uint32_t*)&Qr[(size_t)(g    ) * HDc + c    ];
            qf[kg][1] = *(const uint32_t*)&Qr[(size_t)(g + 8) * HDc + c    ];
            qf[kg][2] = *(const uint32_t*)&Qr[(size_t)(g    ) * HDc + c + 8];
            qf[kg][3] = *(const uint32_t*)&Qr[(size_t)(g + 8) * HDc + c + 8];
        }
    }

    float oacc[8][4];
#pragma unroll
    for (int nt = 0; nt < 8; nt++)
#pragma unroll
        for (int e = 0; e < 4; e++) oacc[nt][e] = 0.f;
    float lacc[4] = {0.f, 0.f, 0.f, 0.f};
    const uint32_t ones[2] = { ONE_H2, ONE_H2 };

    auto issue_kv = [&](int kt, int s) {
#pragma unroll
        for (int i = 0; i < 2; i++) {
            const int idx = tid + (i << 8);
            const int r = idx >> 3, c = (idx & 7) << 3;
            const uint32_t off = (uint32_t)(r * AT_PAD + c) * 2;
            const size_t gsrc = (size_t)(kt * 64 + r) * HDc + c;
            CP16(ks_u[s] + off, Kg + gsrc);
            CP16(vs_u[s] + off, Vg + gsrc);
        }
    };

    issue_kv(0, 0); CP_COMMIT();

    for (int kt = 0; kt < Sc / 64; kt++) {
        const int cur = kt & 1;
        CP_WAIT0();
        __syncthreads();
        if (kt + 1 < Sc / 64) { issue_kv(kt + 1, cur ^ 1); CP_COMMIT(); }

        const __half* Ks = KS[cur];
        const __half* Vs = VS[cur];

        // ---- S' = (log2e/8) Q K^T ----
        float sacc[8][4];
#pragma unroll
        for (int nt = 0; nt < 8; nt++)
#pragma unroll
            for (int e = 0; e < 4; e++) sacc[nt][e] = 0.f;

#pragma unroll
        for (int kg = 0; kg < 4; kg++) {
            const int kb = kg * 16;
#pragma unroll
            for (int ntp = 0; ntp < 4; ntp++) {
                uint32_t kr[4];
                ldm_x4(kr, &Ks[(ntp * 16 + l15) * AT_PAD + kb + lhi]);
                uint32_t b0[2] = { kr[0], kr[2] };
                uint32_t b1[2] = { kr[1], kr[3] };
                mma_f16(sacc[2*ntp    ], qf[kg], b0);
                mma_f16(sacc[2*ntp + 1], qf[kg], b1);
            }
        }

        // ---- P = 2^s ----
        uint32_t ph[8][2];
#pragma unroll
        for (int nt = 0; nt < 8; nt++) {
            ph[nt][0] = ex2_h2(pack_h2(sacc[nt][0], sacc[nt][1]));
            ph[nt][1] = ex2_h2(pack_h2(sacc[nt][2], sacc[nt][3]));
        }

        // ---- O += P V ; l += P @ ones ----
#pragma unroll
        for (int kg = 0; kg < 4; kg++) {
            const int kb = kg * 16;
            uint32_t pf[4] = { ph[2*kg][0], ph[2*kg][1], ph[2*kg+1][0], ph[2*kg+1][1] };
            mma_f16(lacc, pf, ones);
#pragma unroll
            for (int ntp = 0; ntp < 4; ntp++) {
                uint32_t vr[4];
                ldm_x4_trans(vr, &Vs[(kb + l15) * AT_PAD + ntp * 16 + lhi]);
                mma_f16(oacc[2*ntp    ], pf, vr    );
                mma_f16(oacc[2*ntp + 1], pf, vr + 2);
            }
        }
    }

    // ---- epilogue ----
    const float inv0 = 1.0f / lacc[0];
    const float inv1 = 1.0f / lacc[2];
    const int b = bh >> 4, h = bh & 15;
    const int s0 = q0 + rw + g;
    const int s1 = s0 + 8;
#pragma unroll
    for (int nt = 0; nt < 8; nt++) {
        const int col = h * 64 + nt * 8 + 2 * tig;
        *(uint32_t*)&g_atth[(size_t)(b * Sc + s0) * Hc + col] =
            pack_h2(oacc[nt][0] * inv0, oacc[nt][1] * inv0);
        *(uint32_t*)&g_atth[(size_t)(b * Sc + s1) * Hc + col] =
            pack_h2(oacc[nt][2] * inv1, oacc[nt][3] * inv1);
    }
}

// ===========================================================================
// LN kernels.
// ===========================================================================
__global__ void ln_fh(const float* __restrict__ X, const __half* __restrict__ Y,
                      const float* __restrict__ g, const float* __restrict__ bta,
                      __half* __restrict__ out16)
{
    const int row = blockIdx.x;
    const int tid = threadIdx.x;

    float4 a = ((const float4*)(X + (size_t)row * Hc))[tid];
    uint2 yu = *(const uint2*)&Y[(size_t)row * Hc + tid * 4];
    float2 y0 = __half22float2(*(__half2*)&yu.x);
    float2 y1 = __half22float2(*(__half2*)&yu.y);
    float4 s = make_float4(a.x + y0.x, a.y + y0.y, a.z + y1.x, a.w + y1.y);

    float sum = s.x + s.y + s.z + s.w;
    float sq  = s.x*s.x + s.y*s.y + s.z*s.z + s.w*s.w;
#pragma unroll
    for (int off = 1; off < 32; off <<= 1) {
        sum += __shfl_xor_sync(0xffffffffu, sum, off);
        sq  += __shfl_xor_sync(0xffffffffu, sq,  off);
    }
    __shared__ float ssum[8], ssq[8];
    if ((tid & 31) == 0) { ssum[tid >> 5] = sum; ssq[tid >> 5] = sq; }
    __syncthreads();
    float fs = 0.f, fq = 0.f;
#pragma unroll
    for (int w = 0; w < 8; w++) { fs += ssum[w]; fq += ssq[w]; }

    const float mean = fs * (1.0f / Hc);
    const float var  = fq * (1.0f / Hc) - mean * mean;
    const float rstd = rsqrtf(var + 1e-5f);

    float4 gg = ((const float4*)g)[tid];
    float4 bb = ((const float4*)bta)[tid];
    float4 o = make_float4((s.x - mean) * rstd * gg.x + bb.x,
                           (s.y - mean) * rstd * gg.y + bb.y,
                           (s.z - mean) * rstd * gg.z + bb.z,
                           (s.w - mean) * rstd * gg.w + bb.w);
    uint2 u = { pack_h2(o.x, o.y), pack_h2(o.z, o.w) };
    *(uint2*)&out16[(size_t)row * Hc + tid * 4] = u;
}

__global__ void ln_hh(const __half* __restrict__ X, const __half* __restrict__ Y,
                      const float* __restrict__ g, const float* __restrict__ bta,
                      float* __restrict__ out)
{
    const int row = blockIdx.x;
    const int tid = threadIdx.x;

    uint2 xu = *(const uint2*)&X[(size_t)row * Hc + tid * 4];
    uint2 yu = *(const uint2*)&Y[(size_t)row * Hc + tid * 4];
    float2 x0 = __half22float2(*(__half2*)&xu.x);
    float2 x1 = __half22float2(*(__half2*)&xu.y);
    float2 y0 = __half22float2(*(__half2*)&yu.x);
    float2 y1 = __half22float2(*(__half2*)&yu.y);
    float4 s = make_float4(x0.x + y0.x, x0.y + y0.y, x1.x + y1.x, x1.y + y1.y);

    float sum = s.x + s.y + s.z + s.w;
    float sq  = s.x*s.x + s.y*s.y + s.z*s.z + s.w*s.w;
#pragma unroll
    for (int off = 1; off < 32; off <<= 1) {
        sum += __shfl_xor_sync(0xffffffffu, sum, off);
        sq  += __shfl_xor_sync(0xffffffffu, sq,  off);
    }
    __shared__ float ssum[8], ssq[8];
    if ((tid & 31) == 0) { ssum[tid >> 5] = sum; ssq[tid >> 5] = sq; }
    __syncthreads();
    float fs = 0.f, fq = 0.f;
#pragma unroll
    for (int w = 0; w < 8; w++) { fs += ssum[w]; fq += ssq[w]; }

    const float mean = fs * (1.0f / Hc);
    const float var  = fq * (1.0f / Hc) - mean * mean;
    const float rstd = rsqrtf(var + 1e-5f);

    float4 gg = ((const float4*)g)[tid];
    float4 bb = ((const float4*)bta)[tid];
    float4 o = make_float4((s.x - mean) * rstd * gg.x + bb.x,
                           (s.y - mean) * rstd * gg.y + bb.y,
                           (s.z - mean) * rstd * gg.z + bb.z,
                           (s.w - mean) * rstd * gg.w + bb.w);
    ((float4*)(out + (size_t)row * Hc))[tid] = o;
}

// ===========================================================================
extern "C" void kernel_launch(void* const* d_in, const int* in_sizes, int n_in,
                              void* d_out, int out_size)
{
    const float* x  = (const float*)d_in[0];
    const float* Wq = (const float*)d_in[1];
    const float* bq = (const float*)d_in[2];
    const float* Wk = (const float*)d_in[3];
    const float* bk = (const float*)d_in[4];
    const float* Wv = (const float*)d_in[5];
    const float* bv = (const float*)d_in[6];
    const float* Wi = (const float*)d_in[7];
    const float* bi = (const float*)d_in[8];
    const float* Wo = (const float*)d_in[9];
    const float* bo = (const float*)d_in[10];
    const float* g1 = (const float*)d_in[11];
    const float* b1 = (const float*)d_in[12];
    const float* g2 = (const float*)d_in[13];
    const float* b2 = (const float*)d_in[14];
    float* out = (float*)d_out;

    __half *xh, *qh, *kh, *vh, *hh, *ffnh, *atth, *wqkv, *wi, *wo;
    cudaGetSymbolAddress((void**)&xh,   g_xh);
    cudaGetSymbolAddress((void**)&qh,   g_qh);
    cudaGetSymbolAddress((void**)&kh,   g_kh);
    cudaGetSymbolAddress((void**)&vh,   g_vh);
    cudaGetSymbolAddress((void**)&hh,   g_hh);
    cudaGetSymbolAddress((void**)&ffnh, g_ffnh);
    cudaGetSymbolAddress((void**)&atth, g_atth);
    cudaGetSymbolAddress((void**)&wqkv, g_wqkv);
    cudaGetSymbolAddress((void**)&wi,   g_wi);
    cudaGetSymbolAddress((void**)&wo,   g_wo);

    cudaFuncSetAttribute(attn_k,   cudaFuncAttributeMaxDynamicSharedMemorySize, AT_SMEM);
    cudaFuncSetAttribute(mgemm<0>, cudaFuncAttributeMaxDynamicSharedMemorySize, GT_SMEM);
    cudaFuncSetAttribute(mgemm<1>, cudaFuncAttributeMaxDynamicSharedMemorySize, GT_SMEM);
    cudaFuncSetAttribute(mgemm<2>, cudaFuncAttributeMaxDynamicSharedMemorySize, GT_SMEM);

    // activations + weights -> fp16 (streaming, no transpose)
    cvt_h<<<Nc*Hc/(256*8), 256>>>(x, xh);
    cvt_w3<<<dim3(Hc*Hc/(256*8), 1, 3), 256>>>(Wq, Wk, Wv, wqkv);
    cvt_h<<<Hc*FFc/(256*8), 256>>>(Wi, wi);
    cvt_h<<<FFc*Hc/(256*8), 256>>>(Wo, wo);

    // fused QKV projection -> fp16 q(prescaled)/k/v scatter [b,h,s,d]
    mgemm<1><<<dim3(3*Hc/GT_BN, Nc/GT_BM), 256, GT_SMEM>>>(
        xh, wqkv, bq, bk, bv, qh, kh, vh, Hc, 3*Hc);

    // attention -> fp16 atth
    attn_k<<<dim3(Sc / 128, Bc * NHc), 256, AT_SMEM>>>();

    // residual + LN1 -> fp16 hh
    ln_fh<<<Nc, 256>>>(x, atth, g1, b1, hh);

    // FFN (fp16 throughout)
    mgemm<2><<<dim3(FFc/GT_BN, Nc/GT_BM), 256, GT_SMEM>>>(
        hh, wi, bi, bi, bi, ffnh, ffnh, ffnh, Hc, FFc);
    mgemm<0><<<dim3(Hc/GT_BN, Nc/GT_BM), 256, GT_SMEM>>>(
        ffnh, wo, bo, bo, bo, atth, atth, atth, FFc, Hc);

    // residual + LN2 -> final fp32 out
    ln_hh<<<Nc, 256>>>(hh, atth, g2, b2, out);
}

// round 17
// speedup vs baseline: 1.1300x; 1.0128x over previous
#include <cuda_runtime.h>
#include <cuda_fp16.h>
#include <math.h>
#include <stdint.h>

// ---------------------------------------------------------------------------
// Transformer block: x -> QKV -> attention -> +res -> LN1 -> FFN(gelu) -> +res -> LN2
// B=4 S=2048 H=1024 NH=16 HD=64 FF=4096.
// fp32 in/out; fp16 storage + fp16 mma.sync (fp32 accum); cp.async; ldmatrix;
// unnormalized exp2 softmax; l via ones-MMA; 2 CTAs/SM.
// R17: single fused fp32->fp16 conversion launch; LN1 reads fp16 x mirror.
// ---------------------------------------------------------------------------

#define Bc   4
#define Sc   2048
#define Hc   1024
#define NHc  16
#define HDc  64
#define FFc  4096
#define Nc   (Bc*Sc)   // 8192

#define QSCALE 0.1803368801111204f     // (1/sqrt(64)) * log2(e)
#define ONE_H2 0x3C003C00u

__device__ __align__(128) __half g_xh   [Nc*Hc];
__device__ __align__(128) __half g_qh   [Bc*NHc*Sc*HDc];
__device__ __align__(128) __half g_kh   [Bc*NHc*Sc*HDc];
__device__ __align__(128) __half g_vh   [Bc*NHc*Sc*HDc];
__device__ __align__(128) __half g_hh   [Nc*Hc];
__device__ __align__(128) __half g_ffnh [Nc*FFc];
__device__ __align__(128) __half g_atth [Nc*Hc];
__device__ __align__(128) __half g_wqkv [Hc*3*Hc];     // [1024][3072] fp16, native K-major
__device__ __align__(128) __half g_wi   [Hc*FFc];      // [1024][4096]
__device__ __align__(128) __half g_wo   [FFc*Hc];      // [4096][1024]

__device__ __forceinline__ uint32_t pack_h2(float x, float y) {
    __half2 h = __floats2half2_rn(x, y);
    return *(uint32_t*)&h;
}
__device__ __forceinline__ void mma_f16(float* d, const uint32_t* a, const uint32_t* b) {
    asm volatile(
        "mma.sync.aligned.m16n8k16.row.col.f32.f16.f16.f32 "
        "{%0,%1,%2,%3}, {%4,%5,%6,%7}, {%8,%9}, {%0,%1,%2,%3};"
        : "+f"(d[0]), "+f"(d[1]), "+f"(d[2]), "+f"(d[3])
        : "r"(a[0]), "r"(a[1]), "r"(a[2]), "r"(a[3]), "r"(b[0]), "r"(b[1]));
}
__device__ __forceinline__ void ldm_x4(uint32_t* r, const __half* p) {
    uint32_t a = (uint32_t)__cvta_generic_to_shared(p);
    asm volatile("ldmatrix.sync.aligned.m8n8.x4.shared.b16 {%0,%1,%2,%3}, [%4];"
        : "=r"(r[0]), "=r"(r[1]), "=r"(r[2]), "=r"(r[3]) : "r"(a));
}
__device__ __forceinline__ void ldm_x4_trans(uint32_t* r, const __half* p) {
    uint32_t a = (uint32_t)__cvta_generic_to_shared(p);
    asm volatile("ldmatrix.sync.aligned.m8n8.x4.trans.shared.b16 {%0,%1,%2,%3}, [%4];"
        : "=r"(r[0]), "=r"(r[1]), "=r"(r[2]), "=r"(r[3]) : "r"(a));
}
__device__ __forceinline__ uint32_t ex2_h2(uint32_t in) {
    uint32_t o; asm("ex2.approx.f16x2 %0, %1;" : "=r"(o) : "r"(in)); return o;
}

#define CP16(dst_u32, src) \
    asm volatile("cp.async.cg.shared.global [%0], [%1], 16;" :: "r"(dst_u32), "l"(src))
#define CP_COMMIT() asm volatile("cp.async.commit_group;" ::: "memory")
#define CP_WAIT0()  asm volatile("cp.async.wait_group 0;" ::: "memory")
#define CP_WAIT1()  asm volatile("cp.async.wait_group 1;" ::: "memory")

__device__ __forceinline__ float gelu_exact(float x) {
    return 0.5f * x * (1.0f + erff(x * 0.70710678118654752f));
}

// ===========================================================================
// fp16 GEMM (R16): out = A[N,K] @ W[K,M] + bias.  W native K-major fp16.
// Block 128x128x64, 256 thr, warp tile 64x32, 3-stage cp.async, 2 CTAs/SM.
// A frags via ldmatrix; B frags via ldmatrix.trans from [k][m] tile.
// ===========================================================================
#define GT_BM 128
#define GT_BN 128
#define GT_BK 64
#define GT_APAD 72
#define GT_BPAD 136
#define GT_SA (GT_BM*GT_APAD)
#define GT_SB (GT_BK*GT_BPAD)
#define GT_STG (GT_SA+GT_SB)
#define GT_SMEM (3*GT_STG*2)                // 107520 B

template<int MODE>
__global__ __launch_bounds__(256, 2)
void mgemm(const __half* __restrict__ A, const __half* __restrict__ Bw,
           const float* __restrict__ bias0, const float* __restrict__ bias1,
           const float* __restrict__ bias2,
           __half* __restrict__ o0, __half* __restrict__ o1, __half* __restrict__ o2,
           int K, int Mout)
{
    extern __shared__ __half smh[];
    const uint32_t sm_u = (uint32_t)__cvta_generic_to_shared(smh);

    const int tid  = threadIdx.x;
    const int wid  = tid >> 5;
    const int lane = tid & 31;
    const int g    = lane >> 2;
    const int tig  = lane & 3;
    const int wm   = wid & 1;
    const int wn   = wid >> 1;
    const int l15  = lane & 15;
    const int lhi  = (lane >> 4) << 3;

    const int row0 = blockIdx.y * GT_BM;
    const int col0 = blockIdx.x * GT_BN;

    const __half* Ab = A  + (size_t)row0 * K;
    const __half* Bb = Bw + col0;

    float acc[4][4][4];
#pragma unroll
    for (int mt = 0; mt < 4; mt++)
#pragma unroll
        for (int nt = 0; nt < 4; nt++)
#pragma unroll
            for (int e = 0; e < 4; e++) acc[mt][nt][e] = 0.f;

    const int KT = K / GT_BK;

    auto issue = [&](int kt, int s) {
        const __half* ap = Ab + kt * GT_BK;
        const __half* bp = Bb + (size_t)(kt * GT_BK) * Mout;
        const uint32_t abase = sm_u + (uint32_t)(s * GT_STG) * 2;
        const uint32_t bbase = abase + GT_SA * 2;
#pragma unroll
        for (int i = 0; i < 4; i++) {
            const int idx = tid + (i << 8);
            {
                const int r = idx >> 3, c = (idx & 7) << 3;
                CP16(abase + (uint32_t)(r * GT_APAD + c) * 2, ap + (size_t)r * K + c);
            }
            {
                const int r = idx >> 4, c = (idx & 15) << 3;
                CP16(bbase + (uint32_t)(r * GT_BPAD + c) * 2, bp + (size_t)r * Mout + c);
            }
        }
    };

    issue(0, 0); CP_COMMIT();
    issue(1, 1); CP_COMMIT();

    for (int kt = 0; kt < KT; kt++) {
        const int cur = kt % 3;
        if (kt + 1 < KT) CP_WAIT1(); else CP_WAIT0();
        __syncthreads();
        if (kt + 2 < KT) { issue(kt + 2, (kt + 2) % 3); CP_COMMIT(); }

        const __half* As = smh + cur * GT_STG;
        const __half* Bs = As + GT_SA;
#pragma unroll
        for (int ks = 0; ks < 4; ks++) {
            const int kb = ks * 16;
            uint32_t af[4][4], bq[2][4];
#pragma unroll
            for (int mt = 0; mt < 4; mt++)
                ldm_x4(af[mt], &As[(wm * 64 + mt * 16 + l15) * GT_APAD + kb + lhi]);
#pragma unroll
            for (int np = 0; np < 2; np++)
                ldm_x4_trans(bq[np], &Bs[(kb + l15) * GT_BPAD + wn * 32 + np * 16 + lhi]);
#pragma unroll
            for (int mt = 0; mt < 4; mt++)
#pragma unroll
                for (int nt = 0; nt < 4; nt++) {
                    uint32_t bb[2] = { bq[nt >> 1][(nt & 1) * 2], bq[nt >> 1][(nt & 1) * 2 + 1] };
                    mma_f16(acc[mt][nt], af[mt], bb);
                }
        }
    }

    const int trow = row0 + wm * 64 + g;
    const int tcol = col0 + wn * 32 + 2 * tig;

#pragma unroll
    for (int mt = 0; mt < 4; mt++) {
#pragma unroll
        for (int half_ = 0; half_ < 2; half_++) {
            const int row = trow + mt * 16 + half_ * 8;
            const int bb_ = row >> 11, ss_ = row & 2047;
#pragma unroll
            for (int nt = 0; nt < 4; nt++) {
                const int gc = tcol + nt * 8;
                float v0 = acc[mt][nt][half_ * 2 + 0];
                float v1 = acc[mt][nt][half_ * 2 + 1];
                if (MODE == 1) {
                    const int t  = gc >> 10;
                    const int ct = gc & 1023;
                    const float* bp = (t == 0) ? bias0 : (t == 1 ? bias1 : bias2);
                    __half* ob = (t == 0) ? o0 : (t == 1 ? o1 : o2);
                    v0 += bp[ct]; v1 += bp[ct + 1];
                    if (t == 0) { v0 *= QSCALE; v1 *= QSCALE; }
                    const int hh = ct >> 6, d0 = ct & 63;
                    __half* p = ob + (((size_t)(bb_ * NHc + hh) * Sc + ss_) << 6) + d0;
                    *(uint32_t*)p = pack_h2(v0, v1);
                } else {
                    v0 += bias0[gc]; v1 += bias0[gc + 1];
                    if (MODE == 2) { v0 = gelu_exact(v0); v1 = gelu_exact(v1); }
                    *(uint32_t*)(o0 + (size_t)row * Mout + gc) = pack_h2(v0, v1);
                }
            }
        }
    }
}

// ===========================================================================
// Single fused fp32 -> fp16 conversion for x, Wq, Wk, Wv, Wi, Wo.
// One block = 2048 contiguous source elements (256 thr x 8).
// Block ranges: x[0,4096) Wq[4096,4608) Wk[4608,5120) Wv[5120,5632)
//               Wi[5632,7680) Wo[7680,9728)
// Wq/Wk/Wv scatter into interleaved wqkv [1024][3072].
// ===========================================================================
#define CVT_BLOCKS 9728

__global__ __launch_bounds__(256)
void cvt_all(const float* __restrict__ x,
             const float* __restrict__ Wq, const float* __restrict__ Wk,
             const float* __restrict__ Wv, const float* __restrict__ Wi,
             const float* __restrict__ Wo,
             __half* __restrict__ xh, __half* __restrict__ wqkv,
             __half* __restrict__ wi, __half* __restrict__ wo)
{
    const int b = blockIdx.x;
    const int tid = threadIdx.x;

    const float* src;
    int local;          // block index within segment
    int seg;            // 0:x 1..3:Wq/k/v 4:Wi 5:Wo
    if (b < 4096)      { seg = 0; local = b;        src = x;  }
    else if (b < 4608) { seg = 1; local = b - 4096; src = Wq; }
    else if (b < 5120) { seg = 2; local = b - 4608; src = Wk; }
    else if (b < 5632) { seg = 3; local = b - 5120; src = Wv; }
    else if (b < 7680) { seg = 4; local = b - 5632; src = Wi; }
    else               { seg = 5; local = b - 7680; src = Wo; }

    const size_t e = (size_t)local * 2048 + tid * 8;
    float4 a0 = *(const float4*)(src + e);
    float4 a1 = *(const float4*)(src + e + 4);
    uint4 u = { pack_h2(a0.x, a0.y), pack_h2(a0.z, a0.w),
                pack_h2(a1.x, a1.y), pack_h2(a1.z, a1.w) };

    if (seg == 0)      *(uint4*)&xh[e] = u;
    else if (seg == 4) *(uint4*)&wi[e] = u;
    else if (seg == 5) *(uint4*)&wo[e] = u;
    else {
        const int k = (int)(e >> 10), m = (int)(e & 1023);
        *(uint4*)&wqkv[(size_t)k * 3072 + (seg - 1) * 1024 + m] = u;
    }
}

// ===========================================================================
// Flash attention (R13/R16): 256 thr, 8 warps x 16 queries, 64-row KV tiles,
// cp.async dbl-buf, ldmatrix, unnormalized P = 2^s, l via ones-MMA, 2 CTAs/SM.
// ===========================================================================
#define AT_PAD 72
#define AT_TS  (64*AT_PAD)
#define AT_SMEM (4*AT_TS*2)     // 36864 B

__global__ __launch_bounds__(256, 2)
void attn_k()
{
    extern __shared__ __half smh[];
    __half* KS[2] = { smh,            smh + 2*AT_TS };
    __half* VS[2] = { smh + AT_TS,    smh + 3*AT_TS };
    uint32_t ks_u[2], vs_u[2];
    ks_u[0] = (uint32_t)__cvta_generic_to_shared(KS[0]);
    ks_u[1] = (uint32_t)__cvta_generic_to_shared(KS[1]);
    vs_u[0] = (uint32_t)__cvta_generic_to_shared(VS[0]);
    vs_u[1] = (uint32_t)__cvta_generic_to_shared(VS[1]);

    const int bh = blockIdx.y;
    const __half* Qg = g_qh + (size_t)bh * Sc * HDc;
    const __half* Kg = g_kh + (size_t)bh * Sc * HDc;
    const __half* Vg = g_vh + (size_t)bh * Sc * HDc;
    const int q0 = blockIdx.x * 128;

    const int tid  = threadIdx.x;
    const int w    = tid >> 5;
    const int lane = tid & 31;
    const int g    = lane >> 2;
    const int tig  = lane & 3;
    const int rw   = w * 16;
    const int l15  = lane & 15;
    const int lhi  = (lane >> 4) << 3;

    uint32_t qf[4][4];
    {
        const __half* Qr = Qg + (size_t)(q0 + rw) * HDc;
#pragma unroll
        for (int kg = 0; kg < 4; kg++) {
            const int c = kg * 16 + 2 * tig;
            qf[kg][0] = *(const uint32_t*)&Qr[(size_t)(g    ) * HDc + c    ];
            qf[kg][1] = *(const uint32_t*)&Qr[(size_t)(g + 8) * HDc + c    ];
            qf[kg][2] = *(const uint32_t*)&Qr[(size_t)(g    ) * HDc + c + 8];
            qf[kg][3] = *(const uint32_t*)&Qr[(size_t)(g + 8) * HDc + c + 8];
        }
    }

    float oacc[8][4];
#pragma unroll
    for (int nt = 0; nt < 8; nt++)
#pragma unroll
        for (int e = 0; e < 4; e++) oacc[nt][e] = 0.f;
    float lacc[4] = {0.f, 0.f, 0.f, 0.f};
    const uint32_t ones[2] = { ONE_H2, ONE_H2 };

    auto issue_kv = [&](int kt, int s) {
#pragma unroll
        for (int i = 0; i < 2; i++) {
            const int idx = tid + (i << 8);
            const int r = idx >> 3, c = (idx & 7) << 3;
            const uint32_t off = (uint32_t)(r * AT_PAD + c) * 2;
            const size_t gsrc = (size_t)(kt * 64 + r) * HDc + c;
            CP16(ks_u[s] + off, Kg + gsrc);
            CP16(vs_u[s] + off, Vg + gsrc);
        }
    };

    issue_kv(0, 0); CP_COMMIT();

    for (int kt = 0; kt < Sc / 64; kt++) {
        const int cur = kt & 1;
        CP_WAIT0();
        __syncthreads();
        if (kt + 1 < Sc / 64) { issue_kv(kt + 1, cur ^ 1); CP_COMMIT(); }

        const __half* Ks = KS[cur];
        const __half* Vs = VS[cur];

        float sacc[8][4];
#pragma unroll
        for (int nt = 0; nt < 8; nt++)
#pragma unroll
            for (int e = 0; e < 4; e++) sacc[nt][e] = 0.f;

#pragma unroll
        for (int kg = 0; kg < 4; kg++) {
            const int kb = kg * 16;
#pragma unroll
            for (int ntp = 0; ntp < 4; ntp++) {
                uint32_t kr[4];
                ldm_x4(kr, &Ks[(ntp * 16 + l15) * AT_PAD + kb + lhi]);
                uint32_t b0[2] = { kr[0], kr[2] };
                uint32_t b1[2] = { kr[1], kr[3] };
                mma_f16(sacc[2*ntp    ], qf[kg], b0);
                mma_f16(sacc[2*ntp + 1], qf[kg], b1);
            }
        }

        uint32_t ph[8][2];
#pragma unroll
        for (int nt = 0; nt < 8; nt++) {
            ph[nt][0] = ex2_h2(pack_h2(sacc[nt][0], sacc[nt][1]));
            ph[nt][1] = ex2_h2(pack_h2(sacc[nt][2], sacc[nt][3]));
        }

#pragma unroll
        for (int kg = 0; kg < 4; kg++) {
            const int kb = kg * 16;
            uint32_t pf[4] = { ph[2*kg][0], ph[2*kg][1], ph[2*kg+1][0], ph[2*kg+1][1] };
            mma_f16(lacc, pf, ones);
#pragma unroll
            for (int ntp = 0; ntp < 4; ntp++) {
                uint32_t vr[4];
                ldm_x4_trans(vr, &Vs[(kb + l15) * AT_PAD + ntp * 16 + lhi]);
                mma_f16(oacc[2*ntp    ], pf, vr    );
                mma_f16(oacc[2*ntp + 1], pf, vr + 2);
            }
        }
    }

    const float inv0 = 1.0f / lacc[0];
    const float inv1 = 1.0f / lacc[2];
    const int b = bh >> 4, h = bh & 15;
    const int s0 = q0 + rw + g;
    const int s1 = s0 + 8;
#pragma unroll
    for (int nt = 0; nt < 8; nt++) {
        const int col = h * 64 + nt * 8 + 2 * tig;
        *(uint32_t*)&g_atth[(size_t)(b * Sc + s0) * Hc + col] =
            pack_h2(oacc[nt][0] * inv0, oacc[nt][1] * inv0);
        *(uint32_t*)&g_atth[(size_t)(b * Sc + s1) * Hc + col] =
            pack_h2(oacc[nt][2] * inv1, oacc[nt][3] * inv1);
    }
}

// ===========================================================================
// LN kernels: X fp16 + Y fp16 -> fp16 (LN1) / fp32 (LN2).
// ===========================================================================
template<int OUT16>
__global__ void ln_hh(const __half* __restrict__ X, const __half* __restrict__ Y,
                      const float* __restrict__ g, const float* __restrict__ bta,
                      float* __restrict__ out, __half* __restrict__ out16)
{
    const int row = blockIdx.x;
    const int tid = threadIdx.x;

    uint2 xu = *(const uint2*)&X[(size_t)row * Hc + tid * 4];
    uint2 yu = *(const uint2*)&Y[(size_t)row * Hc + tid * 4];
    float2 x0 = __half22float2(*(__half2*)&xu.x);
    float2 x1 = __half22float2(*(__half2*)&xu.y);
    float2 y0 = __half22float2(*(__half2*)&yu.x);
    float2 y1 = __half22float2(*(__half2*)&yu.y);
    float4 s = make_float4(x0.x + y0.x, x0.y + y0.y, x1.x + y1.x, x1.y + y1.y);

    float sum = s.x + s.y + s.z + s.w;
    float sq  = s.x*s.x + s.y*s.y + s.z*s.z + s.w*s.w;
#pragma unroll
    for (int off = 1; off < 32; off <<= 1) {
        sum += __shfl_xor_sync(0xffffffffu, sum, off);
        sq  += __shfl_xor_sync(0xffffffffu, sq,  off);
    }
    __shared__ float ssum[8], ssq[8];
    if ((tid & 31) == 0) { ssum[tid >> 5] = sum; ssq[tid >> 5] = sq; }
    __syncthreads();
    float fs = 0.f, fq = 0.f;
#pragma unroll
    for (int w = 0; w < 8; w++) { fs += ssum[w]; fq += ssq[w]; }

    const float mean = fs * (1.0f / Hc);
    const float var  = fq * (1.0f / Hc) - mean * mean;
    const float rstd = rsqrtf(var + 1e-5f);

    float4 gg = ((const float4*)g)[tid];
    float4 bb = ((const float4*)bta)[tid];
    float4 o = make_float4((s.x - mean) * rstd * gg.x + bb.x,
                           (s.y - mean) * rstd * gg.y + bb.y,
                           (s.z - mean) * rstd * gg.z + bb.z,
                           (s.w - mean) * rstd * gg.w + bb.w);
    if (OUT16) {
        uint2 u = { pack_h2(o.x, o.y), pack_h2(o.z, o.w) };
        *(uint2*)&out16[(size_t)row * Hc + tid * 4] = u;
    } else {
        ((float4*)(out + (size_t)row * Hc))[tid] = o;
    }
}

// ===========================================================================
extern "C" void kernel_launch(void* const* d_in, const int* in_sizes, int n_in,
                              void* d_out, int out_size)
{
    const float* x  = (const float*)d_in[0];
    const float* Wq = (const float*)d_in[1];
    const float* bq = (const float*)d_in[2];
    const float* Wk = (const float*)d_in[3];
    const float* bk = (const float*)d_in[4];
    const float* Wv = (const float*)d_in[5];
    const float* bv = (const float*)d_in[6];
    const float* Wi = (const float*)d_in[7];
    const float* bi = (const float*)d_in[8];
    const float* Wo = (const float*)d_in[9];
    const float* bo = (const float*)d_in[10];
    const float* g1 = (const float*)d_in[11];
    const float* b1 = (const float*)d_in[12];
    const float* g2 = (const float*)d_in[13];
    const float* b2 = (const float*)d_in[14];
    float* out = (float*)d_out;

    __half *xh, *qh, *kh, *vh, *hh, *ffnh, *atth, *wqkv, *wi, *wo;
    cudaGetSymbolAddress((void**)&xh,   g_xh);
    cudaGetSymbolAddress((void**)&qh,   g_qh);
    cudaGetSymbolAddress((void**)&kh,   g_kh);
    cudaGetSymbolAddress((void**)&vh,   g_vh);
    cudaGetSymbolAddress((void**)&hh,   g_hh);
    cudaGetSymbolAddress((void**)&ffnh, g_ffnh);
    cudaGetSymbolAddress((void**)&atth, g_atth);
    cudaGetSymbolAddress((void**)&wqkv, g_wqkv);
    cudaGetSymbolAddress((void**)&wi,   g_wi);
    cudaGetSymbolAddress((void**)&wo,   g_wo);

    cudaFuncSetAttribute(attn_k,   cudaFuncAttributeMaxDynamicSharedMemorySize, AT_SMEM);
    cudaFuncSetAttribute(mgemm<0>, cudaFuncAttributeMaxDynamicSharedMemorySize, GT_SMEM);
    cudaFuncSetAttribute(mgemm<1>, cudaFuncAttributeMaxDynamicSharedMemorySize, GT_SMEM);
    cudaFuncSetAttribute(mgemm<2>, cudaFuncAttributeMaxDynamicSharedMemorySize, GT_SMEM);

    // all fp32 -> fp16 conversions in one launch
    cvt_all<<<CVT_BLOCKS, 256>>>(x, Wq, Wk, Wv, Wi, Wo, xh, wqkv, wi, wo);

    // fused QKV projection -> fp16 q(prescaled)/k/v scatter [b,h,s,d]
    mgemm<1><<<dim3(3*Hc/GT_BN, Nc/GT_BM), 256, GT_SMEM>>>(
        xh, wqkv, bq, bk, bv, qh, kh, vh, Hc, 3*Hc);

    // attention -> fp16 atth
    attn_k<<<dim3(Sc / 128, Bc * NHc), 256, AT_SMEM>>>();

    // residual + LN1 (fp16 inputs) -> fp16 hh
    ln_hh<1><<<Nc, 256>>>(xh, atth, g1, b1, nullptr, hh);

    // FFN (fp16 throughout)
    mgemm<2><<<dim3(FFc/GT_BN, Nc/GT_BM), 256, GT_SMEM>>>(
        hh, wi, bi, bi, bi, ffnh, ffnh, ffnh, Hc, FFc);
    mgemm<0><<<dim3(Hc/GT_BN, Nc/GT_BM), 256, GT_SMEM>>>(
        ffnh, wo, bo, bo, bo, atth, atth, atth, FFc, Hc);

    // residual + LN2 -> final fp32 out
    ln_hh<0><<<Nc, 256>>>(hh, atth, g2, b2, out, nullptr);
}